// round 2
// baseline (speedup 1.0000x reference)
#include <cuda_runtime.h>

#define BB 16
#define SS 1024
#define DD 768
#define HH 12
#define DH 64

// Scratch (device globals — no allocation allowed)
__device__ float g_Q[(size_t)BB*HH*SS*DH];
__device__ float g_K[(size_t)BB*HH*SS*DH];
__device__ float g_V[(size_t)BB*HH*SS*DH];
__device__ float g_Ctx[(size_t)BB*SS*DD];

// ---------------------------------------------------------------------------
// Kernel 1: QKV projection. grid.x = tile*3 + mat  (S/128 = 8 tiles, 3 mats)
//           grid.y = h, grid.z = b.  Block 256 threads computes 128x64 tile.
// Q/K/V stored as [B,H,S,DH].
// ---------------------------------------------------------------------------
__global__ __launch_bounds__(256) void qkv_kernel(
    const float* __restrict__ X,
    const float* __restrict__ Wq, const float* __restrict__ bq,
    const float* __restrict__ Wk, const float* __restrict__ bk,
    const float* __restrict__ Wv, const float* __restrict__ bv)
{
    const int mat  = blockIdx.x % 3;
    const int tile = blockIdx.x / 3;
    const int h = blockIdx.y, b = blockIdx.z;

    const float* W    = (mat == 0) ? Wq : (mat == 1) ? Wk : Wv;
    const float* bias = (mat == 0) ? bq : (mat == 1) ? bk : bv;
    float* Out        = (mat == 0) ? g_Q : (mat == 1) ? g_K : g_V;

    __shared__ float Xs[128][17];   // 128 rows x 16 k, pad 17
    __shared__ float Ws[16][68];    // 16 k x 64 cols, pad 68 (16B-aligned rows)

    const int tid = threadIdx.x;
    const int tx = tid & 15, ty = tid >> 4;
    const int row0 = tile * 128;

    float acc[8][4];
    #pragma unroll
    for (int i = 0; i < 8; i++)
        #pragma unroll
        for (int j = 0; j < 4; j++) acc[i][j] = 0.f;

    const float* Xb = X + ((size_t)b * SS + row0) * DD;
    const float* Wh = W + (size_t)h * DD * DH;

    for (int k0 = 0; k0 < DD; k0 += 16) {
        #pragma unroll
        for (int i = 0; i < 8; i++) {             // 2048 elems of X tile
            int idx = tid + i * 256;
            int r = idx >> 4, kk = idx & 15;
            Xs[r][kk] = Xb[(size_t)r * DD + k0 + kk];
        }
        #pragma unroll
        for (int i = 0; i < 4; i++) {             // 1024 elems of W tile
            int idx = tid + i * 256;
            int kk = idx >> 6, c = idx & 63;
            Ws[kk][c] = Wh[(size_t)(k0 + kk) * DH + c];
        }
        __syncthreads();
        #pragma unroll
        for (int kk = 0; kk < 16; kk++) {
            float bv4[4];
            *(float4*)bv4 = *(const float4*)&Ws[kk][tx * 4];
            float a[8];
            #pragma unroll
            for (int i = 0; i < 8; i++) a[i] = Xs[ty * 8 + i][kk];
            #pragma unroll
            for (int i = 0; i < 8; i++)
                #pragma unroll
                for (int j = 0; j < 4; j++)
                    acc[i][j] = fmaf(a[i], bv4[j], acc[i][j]);
        }
        __syncthreads();
    }

    float bb[4];
    *(float4*)bb = *(const float4*)&bias[h * DH + tx * 4];
    float* Ob = Out + (((size_t)b * HH + h) * SS + row0) * DH;
    #pragma unroll
    for (int i = 0; i < 8; i++) {
        int r = ty * 8 + i;
        float4 v = make_float4(acc[i][0] + bb[0], acc[i][1] + bb[1],
                               acc[i][2] + bb[2], acc[i][3] + bb[3]);
        *(float4*)&Ob[(size_t)r * DH + tx * 4] = v;
    }
}

// ---------------------------------------------------------------------------
// Kernel 2: flash attention. grid (S/64, H, B), 256 threads.
// 64 query rows per block, loops over 16 key tiles of 64. Online softmax.
// SMEM: Qs[64][64] | KPs[64][68] (K^T, then reused as P) | Vs[64][64]
// Writes context (head-concat) to g_Ctx as [B,S,D].
// ---------------------------------------------------------------------------
#define ATTN_SMEM_FLOATS (64*64 + 64*68 + 64*64)

__global__ __launch_bounds__(256) void attn_kernel()
{
    extern __shared__ float sm[];
    float* Qs  = sm;                 // stride 64
    float* KPs = sm + 64 * 64;       // stride 68
    float* Vs  = KPs + 64 * 68;      // stride 64

    const int tid = threadIdx.x;
    const int tx = tid & 15, ty = tid >> 4;
    const int q0 = blockIdx.x * 64;
    const int h = blockIdx.y, b = blockIdx.z;

    const float* Qg = g_Q + (((size_t)b * HH + h) * SS + q0) * DH;
    const float* Kg = g_K + (((size_t)b * HH + h) * SS) * DH;
    const float* Vg = g_V + (((size_t)b * HH + h) * SS) * DH;

    #pragma unroll
    for (int i = 0; i < 16; i++) {       // Q tile, layout identical
        int idx = tid + i * 256;
        Qs[idx] = Qg[idx];
    }

    float m[4], l[4], o[4][4];
    #pragma unroll
    for (int i = 0; i < 4; i++) {
        m[i] = -1e30f; l[i] = 0.f;
        #pragma unroll
        for (int j = 0; j < 4; j++) o[i][j] = 0.f;
    }

    const float scale = 0.125f;          // 1/sqrt(64)

    for (int kt = 0; kt < SS; kt += 64) {
        __syncthreads();                 // prev iter done reading KPs/Vs
        #pragma unroll
        for (int i = 0; i < 16; i++) {   // K tile, transposed: KPs[d][key]
            int idx = tid + i * 256;
            int key = idx >> 6, d = idx & 63;
            KPs[d * 68 + key] = Kg[(size_t)(kt + key) * DH + d];
        }
        #pragma unroll
        for (int i = 0; i < 16; i++) {   // V tile direct: Vs[key][d]
            int idx = tid + i * 256;
            int key = idx >> 6, d = idx & 63;
            Vs[key * 64 + d] = Vg[(size_t)(kt + key) * DH + d];
        }
        __syncthreads();

        // S = Q @ K^T (scaled)
        float s[4][4];
        #pragma unroll
        for (int i = 0; i < 4; i++)
            #pragma unroll
            for (int j = 0; j < 4; j++) s[i][j] = 0.f;
        #pragma unroll 8
        for (int d = 0; d < 64; d++) {
            float bv4[4];
            *(float4*)bv4 = *(const float4*)&KPs[d * 68 + tx * 4];
            float a[4];
            #pragma unroll
            for (int i = 0; i < 4; i++) a[i] = Qs[(ty * 4 + i) * 64 + d];
            #pragma unroll
            for (int i = 0; i < 4; i++)
                #pragma unroll
                for (int j = 0; j < 4; j++)
                    s[i][j] = fmaf(a[i], bv4[j], s[i][j]);
        }
        __syncthreads();                 // done reading K^T, may overwrite as P

        // online softmax (row groups are 16-lane halves of a warp)
        #pragma unroll
        for (int i = 0; i < 4; i++) {
            #pragma unroll
            for (int j = 0; j < 4; j++) s[i][j] *= scale;
            float mx = fmaxf(fmaxf(s[i][0], s[i][1]), fmaxf(s[i][2], s[i][3]));
            #pragma unroll
            for (int msk = 8; msk >= 1; msk >>= 1)
                mx = fmaxf(mx, __shfl_xor_sync(0xffffffffu, mx, msk));
            float mnew = fmaxf(m[i], mx);
            float alpha = __expf(m[i] - mnew);
            float rsum = 0.f;
            #pragma unroll
            for (int j = 0; j < 4; j++) {
                float p = __expf(s[i][j] - mnew);
                s[i][j] = p; rsum += p;
            }
            #pragma unroll
            for (int msk = 8; msk >= 1; msk >>= 1)
                rsum += __shfl_xor_sync(0xffffffffu, rsum, msk);
            l[i] = l[i] * alpha + rsum;
            m[i] = mnew;
            #pragma unroll
            for (int j = 0; j < 4; j++) o[i][j] *= alpha;
        }

        // stage P into SMEM (aliases the K^T buffer)
        #pragma unroll
        for (int i = 0; i < 4; i++)
            *(float4*)&KPs[(ty * 4 + i) * 68 + tx * 4] = *(float4*)s[i];
        __syncthreads();

        // O += P @ V
        #pragma unroll 8
        for (int k = 0; k < 64; k++) {
            float bv4[4];
            *(float4*)bv4 = *(const float4*)&Vs[k * 64 + tx * 4];
            float a[4];
            #pragma unroll
            for (int i = 0; i < 4; i++) a[i] = KPs[(ty * 4 + i) * 68 + k];
            #pragma unroll
            for (int i = 0; i < 4; i++)
                #pragma unroll
                for (int j = 0; j < 4; j++)
                    o[i][j] = fmaf(a[i], bv4[j], o[i][j]);
        }
    }

    // normalize and write context (head-concat layout [B,S,D])
    float* Cg = g_Ctx + ((size_t)b * SS + q0) * DD + h * DH;
    #pragma unroll
    for (int i = 0; i < 4; i++) {
        float inv = 1.0f / l[i];
        float4 v = make_float4(o[i][0] * inv, o[i][1] * inv,
                               o[i][2] * inv, o[i][3] * inv);
        *(float4*)&Cg[(size_t)(ty * 4 + i) * DD + tx * 4] = v;
    }
}

// ---------------------------------------------------------------------------
// Kernel 3: output projection. out[16384,768] = Ctx @ Wo + bo
// grid (128, 12), 128x64 tiles, 256 threads.
// ---------------------------------------------------------------------------
__global__ __launch_bounds__(256) void proj_kernel(
    const float* __restrict__ Wo, const float* __restrict__ bo,
    float* __restrict__ out)
{
    __shared__ float As[128][17];
    __shared__ float Bs[16][68];

    const int tid = threadIdx.x;
    const int tx = tid & 15, ty = tid >> 4;
    const int row0 = blockIdx.x * 128;
    const int col0 = blockIdx.y * 64;

    float acc[8][4];
    #pragma unroll
    for (int i = 0; i < 8; i++)
        #pragma unroll
        for (int j = 0; j < 4; j++) acc[i][j] = 0.f;

    const float* A = g_Ctx + (size_t)row0 * DD;

    for (int k0 = 0; k0 < DD; k0 += 16) {
        #pragma unroll
        for (int i = 0; i < 8; i++) {
            int idx = tid + i * 256;
            int r = idx >> 4, kk = idx & 15;
            As[r][kk] = A[(size_t)r * DD + k0 + kk];
        }
        #pragma unroll
        for (int i = 0; i < 4; i++) {
            int idx = tid + i * 256;
            int kk = idx >> 6, c = idx & 63;
            Bs[kk][c] = Wo[(size_t)(k0 + kk) * DD + col0 + c];
        }
        __syncthreads();
        #pragma unroll
        for (int kk = 0; kk < 16; kk++) {
            float bv4[4];
            *(float4*)bv4 = *(const float4*)&Bs[kk][tx * 4];
            float a[8];
            #pragma unroll
            for (int i = 0; i < 8; i++) a[i] = As[ty * 8 + i][kk];
            #pragma unroll
            for (int i = 0; i < 8; i++)
                #pragma unroll
                for (int j = 0; j < 4; j++)
                    acc[i][j] = fmaf(a[i], bv4[j], acc[i][j]);
        }
        __syncthreads();
    }

    float bb[4];
    *(float4*)bb = *(const float4*)&bo[col0 + tx * 4];
    #pragma unroll
    for (int i = 0; i < 8; i++) {
        int r = row0 + ty * 8 + i;
        float4 v = make_float4(acc[i][0] + bb[0], acc[i][1] + bb[1],
                               acc[i][2] + bb[2], acc[i][3] + bb[3]);
        *(float4*)&out[(size_t)r * DD + col0 + tx * 4] = v;
    }
}

// ---------------------------------------------------------------------------
extern "C" void kernel_launch(void* const* d_in, const int* in_sizes, int n_in,
                              void* d_out, int out_size)
{
    const float* X  = (const float*)d_in[0];
    const float* Wq = (const float*)d_in[1];
    const float* bq = (const float*)d_in[2];
    const float* Wk = (const float*)d_in[3];
    const float* bk = (const float*)d_in[4];
    const float* Wv = (const float*)d_in[5];
    const float* bv = (const float*)d_in[6];
    const float* Wo = (const float*)d_in[7];
    const float* bo = (const float*)d_in[8];
    float* out = (float*)d_out;

    const int attn_smem = ATTN_SMEM_FLOATS * (int)sizeof(float);  // 50176 B
    cudaFuncSetAttribute(attn_kernel,
                         cudaFuncAttributeMaxDynamicSharedMemorySize, attn_smem);

    qkv_kernel<<<dim3(24, HH, BB), 256>>>(X, Wq, bq, Wk, bk, Wv, bv);
    attn_kernel<<<dim3(SS / 64, HH, BB), 256, attn_smem>>>();
    proj_kernel<<<dim3(SS * BB / 128, DD / 64), 256>>>(Wo, bo, out);
}

// round 4
// speedup vs baseline: 2.7976x; 2.7976x over previous
#include <cuda_runtime.h>
#include <cstdint>

#define BB 16
#define SS 1024
#define DD 768
#define HH 12
#define DH 64

// Scratch (device globals — no allocation allowed)
__device__ float g_Q[(size_t)BB*HH*SS*DH];
__device__ float g_K[(size_t)BB*HH*SS*DH];
__device__ float g_V[(size_t)BB*HH*SS*DH];
__device__ float g_Ctx[(size_t)BB*SS*DD];
__device__ float g_Wt[(size_t)HH*192*DD];   // [h][mat*64+e][d], tf32-rounded
__device__ float g_Wot[(size_t)DD*DD];      // [n][k], tf32-rounded

// ============================ helpers ======================================
__device__ __forceinline__ float tf32r(float x){
    uint32_t u; asm("cvt.rna.tf32.f32 %0, %1;" : "=r"(u) : "f"(x));
    return __uint_as_float(u);
}
__device__ __forceinline__ void mma_tf32(float* c, const uint32_t* a, const uint32_t* b){
    asm volatile(
        "mma.sync.aligned.m16n8k8.row.col.f32.tf32.tf32.f32 "
        "{%0,%1,%2,%3}, {%4,%5,%6,%7}, {%8,%9}, {%0,%1,%2,%3};"
        : "+f"(c[0]), "+f"(c[1]), "+f"(c[2]), "+f"(c[3])
        : "r"(a[0]), "r"(a[1]), "r"(a[2]), "r"(a[3]), "r"(b[0]), "r"(b[1]));
}
__device__ __forceinline__ uint32_t f2u(float x){ return __float_as_uint(x); }

// ===================== weight prep (transpose + tf32 round) ================
__global__ void prep_wqkv(const float* __restrict__ Wq,
                          const float* __restrict__ Wk,
                          const float* __restrict__ Wv)
{
    const int h = blockIdx.x, mat = blockIdx.y;
    const float* W = ((mat == 0) ? Wq : (mat == 1) ? Wk : Wv) + (size_t)h * DD * DH;
    float* Out = g_Wt + ((size_t)h * 192 + mat * 64) * DD;
    for (int i = threadIdx.x; i < DH * DD; i += blockDim.x) {
        int e = i / DD, d = i % DD;
        Out[i] = tf32r(W[(size_t)d * DH + e]);
    }
}
__global__ void prep_wo(const float* __restrict__ Wo)
{
    const int n = blockIdx.x;
    for (int k = threadIdx.x; k < DD; k += blockDim.x)
        g_Wot[(size_t)n * DD + k] = tf32r(Wo[(size_t)k * DD + n]);
}

// =========================================================================
// Shared tf32 mma GEMM body: C[128 x 64] = A[128 x 768] * B[64 x 768]^T
// 256 threads = 8 warps as 2(m) x 4(n). Each warp: 64 rows x 16 cols.
// As[128][36], Bs[64][36] (K-chunk = 32, pad 36 -> conflict-free 4g+t).
// =========================================================================
struct GemmAcc { float c[4][2][4]; };

__device__ __forceinline__ void gemm_body(
    const float* __restrict__ A,     // row-major [*, DD], rows = 128
    const float* __restrict__ Bt,    // [64][DD] n-major (pre-rounded tf32)
    float* As, float* Bs, GemmAcc& acc, bool roundA)
{
    const int tid = threadIdx.x;
    const int w = tid >> 5, lane = tid & 31;
    const int g = lane >> 2, t = lane & 3;
    const int wm = (w >> 2) * 64, wn = (w & 3) * 16;

    #pragma unroll
    for (int mt = 0; mt < 4; mt++)
        #pragma unroll
        for (int nt = 0; nt < 2; nt++)
            #pragma unroll
            for (int i = 0; i < 4; i++) acc.c[mt][nt][i] = 0.f;

    for (int c0 = 0; c0 < 24; c0++) {
        const int k0 = c0 * 32;
        // stage A: 128 rows x 32 floats = 1024 float4 -> 4/thread
        #pragma unroll
        for (int i = 0; i < 4; i++) {
            int fid = tid + i * 256; int r = fid >> 3, u = fid & 7;
            float4 v = *(const float4*)(A + (size_t)r * DD + k0 + u * 4);
            if (roundA) { v.x = tf32r(v.x); v.y = tf32r(v.y); v.z = tf32r(v.z); v.w = tf32r(v.w); }
            *(float4*)(As + r * 36 + u * 4) = v;
        }
        // stage B: 64 rows x 32 floats = 512 float4 -> 2/thread
        #pragma unroll
        for (int i = 0; i < 2; i++) {
            int fid = tid + i * 256; int r = fid >> 3, u = fid & 7;
            *(float4*)(Bs + r * 36 + u * 4) =
                *(const float4*)(Bt + (size_t)r * DD + k0 + u * 4);
        }
        __syncthreads();

        #pragma unroll
        for (int ks = 0; ks < 4; ks++) {
            uint32_t af[4][4], bf[2][2];
            #pragma unroll
            for (int mt = 0; mt < 4; mt++) {
                const float* Ar = As + (wm + mt * 16 + g) * 36 + ks * 8 + t;
                af[mt][0] = f2u(Ar[0]);
                af[mt][1] = f2u(Ar[8 * 36]);
                af[mt][2] = f2u(Ar[4]);
                af[mt][3] = f2u(Ar[8 * 36 + 4]);
            }
            #pragma unroll
            for (int nt = 0; nt < 2; nt++) {
                const float* Br = Bs + (wn + nt * 8 + g) * 36 + ks * 8 + t;
                bf[nt][0] = f2u(Br[0]);
                bf[nt][1] = f2u(Br[4]);
            }
            #pragma unroll
            for (int mt = 0; mt < 4; mt++)
                #pragma unroll
                for (int nt = 0; nt < 2; nt++)
                    mma_tf32(acc.c[mt][nt], af[mt], bf[nt]);
        }
        __syncthreads();
    }
}

// ============================ QKV projection ===============================
// grid (24, 12, 16): blockIdx.x = m_tile*3 + mat; 128 rows x 64 cols.
__global__ __launch_bounds__(256) void qkv_tc(
    const float* __restrict__ X,
    const float* __restrict__ bq, const float* __restrict__ bk,
    const float* __restrict__ bv)
{
    __shared__ float As[128 * 36];
    __shared__ float Bs[64 * 36];

    const int mat = blockIdx.x % 3, m_tile = blockIdx.x / 3;
    const int h = blockIdx.y, b = blockIdx.z;
    const int row0 = m_tile * 128;
    const int tid = threadIdx.x;
    const int w = tid >> 5, lane = tid & 31;
    const int g = lane >> 2, t = lane & 3;
    const int wm = (w >> 2) * 64, wn = (w & 3) * 16;

    GemmAcc acc;
    gemm_body(X + ((size_t)b * SS + row0) * DD,
              g_Wt + ((size_t)h * 192 + mat * 64) * DD, As, Bs, acc, true);

    const float* bp = (mat == 0) ? bq : (mat == 1) ? bk : bv;
    float* Ob = ((mat == 0) ? g_Q : (mat == 1) ? g_K : g_V)
              + (((size_t)b * HH + h) * SS + row0) * DH;
    #pragma unroll
    for (int nt = 0; nt < 2; nt++) {
        int e = wn + nt * 8 + 2 * t;
        float b0 = bp[h * DH + e], b1 = bp[h * DH + e + 1];
        #pragma unroll
        for (int mt = 0; mt < 4; mt++) {
            int r = wm + mt * 16 + g;
            *(float2*)&Ob[(size_t)r * DH + e] =
                make_float2(acc.c[mt][nt][0] + b0, acc.c[mt][nt][1] + b1);
            *(float2*)&Ob[(size_t)(r + 8) * DH + e] =
                make_float2(acc.c[mt][nt][2] + b0, acc.c[mt][nt][3] + b1);
        }
    }
}

// ============================ output projection ============================
// grid (128, 12): 128 rows x 64 cols of out = Ctx @ Wo + bo
__global__ __launch_bounds__(256) void proj_tc(
    const float* __restrict__ bo, float* __restrict__ out)
{
    __shared__ float As[128 * 36];
    __shared__ float Bs[64 * 36];

    const int row0 = blockIdx.x * 128, col0 = blockIdx.y * 64;
    const int tid = threadIdx.x;
    const int w = tid >> 5, lane = tid & 31;
    const int g = lane >> 2, t = lane & 3;
    const int wm = (w >> 2) * 64, wn = (w & 3) * 16;

    GemmAcc acc;
    gemm_body(g_Ctx + (size_t)row0 * DD, g_Wot + (size_t)col0 * DD,
              As, Bs, acc, true);

    #pragma unroll
    for (int nt = 0; nt < 2; nt++) {
        int e = col0 + wn + nt * 8 + 2 * t;
        float b0 = bo[e], b1 = bo[e + 1];
        #pragma unroll
        for (int mt = 0; mt < 4; mt++) {
            int r = row0 + wm + mt * 16 + g;
            *(float2*)&out[(size_t)r * DD + e] =
                make_float2(acc.c[mt][nt][0] + b0, acc.c[mt][nt][1] + b1);
            *(float2*)&out[(size_t)(r + 8) * DD + e] =
                make_float2(acc.c[mt][nt][2] + b0, acc.c[mt][nt][3] + b1);
        }
    }
}

// =========================================================================
// Flash attention with tf32 mma. grid (8, 12, 16), 256 threads (8 warps).
// Each warp owns 16 query rows (m16). Key loop: 16 tiles of 64 keys.
// SMEM: Qs[128][68] (Q*0.125, tf32) | Ks[64][68] | Vs[64][72] | Ps[8][16][68]
// =========================================================================
#define QS_STRIDE 68
#define KS_STRIDE 68
#define VS_STRIDE 72
#define PS_STRIDE 68
#define ATTN_SMEM_BYTES ((128*QS_STRIDE + 64*KS_STRIDE + 64*VS_STRIDE + 8*16*PS_STRIDE) * 4)

__global__ __launch_bounds__(256) void attn_tc()
{
    extern __shared__ float sm[];
    float* Qs = sm;                               // 128 x 68
    float* Ks = Qs + 128 * QS_STRIDE;             // 64 x 68
    float* Vs = Ks + 64 * KS_STRIDE;              // 64 x 72
    float* Ps = Vs + 64 * VS_STRIDE;              // 8 warps x 16 x 68

    const int tid = threadIdx.x;
    const int w = tid >> 5, lane = tid & 31;
    const int g = lane >> 2, t = lane & 3;
    const int q0 = blockIdx.x * 128;
    const int h = blockIdx.y, b = blockIdx.z;

    const float* Qg = g_Q + (((size_t)b * HH + h) * SS + q0) * DH;
    const float* Kg = g_K + (((size_t)b * HH + h) * SS) * DH;
    const float* Vg = g_V + (((size_t)b * HH + h) * SS) * DH;

    // stage Q (scaled by 1/8, tf32-rounded): 2048 float4 -> 8/thread
    #pragma unroll
    for (int i = 0; i < 8; i++) {
        int fid = tid + i * 256; int r = fid >> 4, u = fid & 15;
        float4 v = *(const float4*)(Qg + (size_t)r * DH + u * 4);
        v.x = tf32r(v.x * 0.125f); v.y = tf32r(v.y * 0.125f);
        v.z = tf32r(v.z * 0.125f); v.w = tf32r(v.w * 0.125f);
        *(float4*)(Qs + r * QS_STRIDE + u * 4) = v;
    }

    float m0 = -1e30f, m1 = -1e30f, l0 = 0.f, l1 = 0.f;
    float o[8][4];
    #pragma unroll
    for (int i = 0; i < 8; i++)
        #pragma unroll
        for (int j = 0; j < 4; j++) o[i][j] = 0.f;

    float* Psw = Ps + w * 16 * PS_STRIDE;

    for (int kt = 0; kt < SS; kt += 64) {
        __syncthreads();
        // stage K, V (tf32-rounded): 1024 float4 each -> 4/thread each
        #pragma unroll
        for (int i = 0; i < 4; i++) {
            int fid = tid + i * 256; int r = fid >> 4, u = fid & 15;
            float4 v = *(const float4*)(Kg + (size_t)(kt + r) * DH + u * 4);
            v.x = tf32r(v.x); v.y = tf32r(v.y); v.z = tf32r(v.z); v.w = tf32r(v.w);
            *(float4*)(Ks + r * KS_STRIDE + u * 4) = v;
        }
        #pragma unroll
        for (int i = 0; i < 4; i++) {
            int fid = tid + i * 256; int r = fid >> 4, u = fid & 15;
            float4 v = *(const float4*)(Vg + (size_t)(kt + r) * DH + u * 4);
            v.x = tf32r(v.x); v.y = tf32r(v.y); v.z = tf32r(v.z); v.w = tf32r(v.w);
            *(float4*)(Vs + r * VS_STRIDE + u * 4) = v;
        }
        __syncthreads();

        // S = Qs @ Ks^T : m16 x n64 per warp, k = 64
        float s[8][4];
        #pragma unroll
        for (int nt = 0; nt < 8; nt++)
            #pragma unroll
            for (int j = 0; j < 4; j++) s[nt][j] = 0.f;
        #pragma unroll
        for (int ks = 0; ks < 8; ks++) {
            uint32_t af[4];
            const float* Ar = Qs + (w * 16 + g) * QS_STRIDE + ks * 8 + t;
            af[0] = f2u(Ar[0]); af[1] = f2u(Ar[8 * QS_STRIDE]);
            af[2] = f2u(Ar[4]); af[3] = f2u(Ar[8 * QS_STRIDE + 4]);
            #pragma unroll
            for (int nt = 0; nt < 8; nt++) {
                uint32_t bf[2];
                const float* Br = Ks + (nt * 8 + g) * KS_STRIDE + ks * 8 + t;
                bf[0] = f2u(Br[0]); bf[1] = f2u(Br[4]);
                mma_tf32(s[nt], af, bf);
            }
        }

        // online softmax: rows g (s[.][0..1]) and g+8 (s[.][2..3])
        float mx0 = -1e30f, mx1 = -1e30f;
        #pragma unroll
        for (int nt = 0; nt < 8; nt++) {
            mx0 = fmaxf(mx0, fmaxf(s[nt][0], s[nt][1]));
            mx1 = fmaxf(mx1, fmaxf(s[nt][2], s[nt][3]));
        }
        #pragma unroll
        for (int msk = 1; msk <= 2; msk <<= 1) {
            mx0 = fmaxf(mx0, __shfl_xor_sync(0xffffffffu, mx0, msk));
            mx1 = fmaxf(mx1, __shfl_xor_sync(0xffffffffu, mx1, msk));
        }
        float mn0 = fmaxf(m0, mx0), mn1 = fmaxf(m1, mx1);
        float a0 = __expf(m0 - mn0), a1 = __expf(m1 - mn1);
        float rs0 = 0.f, rs1 = 0.f;
        #pragma unroll
        for (int nt = 0; nt < 8; nt++) {
            float p0 = tf32r(__expf(s[nt][0] - mn0));
            float p1 = tf32r(__expf(s[nt][1] - mn0));
            float p2 = tf32r(__expf(s[nt][2] - mn1));
            float p3 = tf32r(__expf(s[nt][3] - mn1));
            rs0 += p0 + p1; rs1 += p2 + p3;
            *(float2*)(Psw + g * PS_STRIDE + nt * 8 + 2 * t)       = make_float2(p0, p1);
            *(float2*)(Psw + (g + 8) * PS_STRIDE + nt * 8 + 2 * t) = make_float2(p2, p3);
        }
        #pragma unroll
        for (int msk = 1; msk <= 2; msk <<= 1) {
            rs0 += __shfl_xor_sync(0xffffffffu, rs0, msk);
            rs1 += __shfl_xor_sync(0xffffffffu, rs1, msk);
        }
        l0 = l0 * a0 + rs0; l1 = l1 * a1 + rs1;
        m0 = mn0; m1 = mn1;
        #pragma unroll
        for (int nt = 0; nt < 8; nt++) {
            o[nt][0] *= a0; o[nt][1] *= a0;
            o[nt][2] *= a1; o[nt][3] *= a1;
        }
        __syncwarp();

        // O += P @ V : m16 x n64, k = 64 keys
        #pragma unroll
        for (int ks = 0; ks < 8; ks++) {
            uint32_t af[4];
            const float* Ar = Psw + g * PS_STRIDE + ks * 8 + t;
            af[0] = f2u(Ar[0]); af[1] = f2u(Ar[8 * PS_STRIDE]);
            af[2] = f2u(Ar[4]); af[3] = f2u(Ar[8 * PS_STRIDE + 4]);
            #pragma unroll
            for (int nt = 0; nt < 8; nt++) {
                uint32_t bf[2];
                const float* Br = Vs + (ks * 8 + t) * VS_STRIDE + nt * 8 + g;
                bf[0] = f2u(Br[0]); bf[1] = f2u(Br[4 * VS_STRIDE]);
                mma_tf32(o[nt], af, bf);
            }
        }
    }

    // normalize + write context [B,S,D] head-concat
    float inv0 = 1.0f / l0, inv1 = 1.0f / l1;
    float* Cg = g_Ctx + ((size_t)b * SS + q0) * DD + h * DH;
    #pragma unroll
    for (int nt = 0; nt < 8; nt++) {
        int r = w * 16 + g, e = nt * 8 + 2 * t;
        *(float2*)&Cg[(size_t)r * DD + e] =
            make_float2(o[nt][0] * inv0, o[nt][1] * inv0);
        *(float2*)&Cg[(size_t)(r + 8) * DD + e] =
            make_float2(o[nt][2] * inv1, o[nt][3] * inv1);
    }
}

// ---------------------------------------------------------------------------
extern "C" void kernel_launch(void* const* d_in, const int* in_sizes, int n_in,
                              void* d_out, int out_size)
{
    const float* X  = (const float*)d_in[0];
    const float* Wq = (const float*)d_in[1];
    const float* bq = (const float*)d_in[2];
    const float* Wk = (const float*)d_in[3];
    const float* bk = (const float*)d_in[4];
    const float* Wv = (const float*)d_in[5];
    const float* bv = (const float*)d_in[6];
    const float* Wo = (const float*)d_in[7];
    const float* bo = (const float*)d_in[8];
    float* out = (float*)d_out;

    cudaFuncSetAttribute(attn_tc,
                         cudaFuncAttributeMaxDynamicSharedMemorySize, ATTN_SMEM_BYTES);

    prep_wqkv<<<dim3(HH, 3), 256>>>(Wq, Wk, Wv);
    prep_wo<<<DD, 256>>>(Wo);
    qkv_tc<<<dim3(24, HH, BB), 256>>>(X, bq, bk, bv);
    attn_tc<<<dim3(SS / 128, HH, BB), 256, ATTN_SMEM_BYTES>>>();
    proj_tc<<<dim3(SS * BB / 128, DD / 64), 256>>>(bo, out);
}

// round 5
// speedup vs baseline: 3.1635x; 1.1308x over previous
#include <cuda_runtime.h>
#include <cstdint>

#define BB 16
#define SS 1024
#define DD 768
#define HH 12
#define DH 64

// Scratch (device globals — no allocation allowed)
__device__ float g_Q[(size_t)BB*HH*SS*DH];
__device__ float g_K[(size_t)BB*HH*SS*DH];
__device__ float g_V[(size_t)BB*HH*SS*DH];
__device__ float g_Ctx[(size_t)BB*SS*DD];
__device__ float g_Xr[(size_t)BB*SS*DD];    // tf32-rounded X
__device__ float g_Wt[(size_t)HH*192*DD];   // [h][mat*64+e][d], tf32-rounded
__device__ float g_Wot[(size_t)DD*DD];      // [n][k], tf32-rounded

// ============================ helpers ======================================
__device__ __forceinline__ float tf32r(float x){
    uint32_t u; asm("cvt.rna.tf32.f32 %0, %1;" : "=r"(u) : "f"(x));
    return __uint_as_float(u);
}
__device__ __forceinline__ void mma_tf32(float* c, const uint32_t* a, const uint32_t* b){
    asm volatile(
        "mma.sync.aligned.m16n8k8.row.col.f32.tf32.tf32.f32 "
        "{%0,%1,%2,%3}, {%4,%5,%6,%7}, {%8,%9}, {%0,%1,%2,%3};"
        : "+f"(c[0]), "+f"(c[1]), "+f"(c[2]), "+f"(c[3])
        : "r"(a[0]), "r"(a[1]), "r"(a[2]), "r"(a[3]), "r"(b[0]), "r"(b[1]));
}
__device__ __forceinline__ uint32_t f2u(float x){ return __float_as_uint(x); }
__device__ __forceinline__ uint32_t smem_u32(const void* p){
    uint32_t a;
    asm("{ .reg .u64 t; cvta.to.shared.u64 t, %1; cvt.u32.u64 %0, t; }"
        : "=r"(a) : "l"(p));
    return a;
}
__device__ __forceinline__ void cpa16(uint32_t dst, const float* src){
    asm volatile("cp.async.cg.shared.global [%0], [%1], 16;" :: "r"(dst), "l"(src));
}
#define CP_COMMIT() asm volatile("cp.async.commit_group;" ::: "memory")
#define CP_WAIT1()  asm volatile("cp.async.wait_group 1;" ::: "memory")
#define CP_WAIT0()  asm volatile("cp.async.wait_group 0;" ::: "memory")

// ===================== prep kernels ========================================
__global__ void prep_x(const float* __restrict__ X)
{
    size_t i = ((size_t)blockIdx.x * 256 + threadIdx.x) * 4;
    float4 v = *(const float4*)(X + i);
    v.x = tf32r(v.x); v.y = tf32r(v.y); v.z = tf32r(v.z); v.w = tf32r(v.w);
    *(float4*)(g_Xr + i) = v;
}
__global__ void prep_wqkv(const float* __restrict__ Wq,
                          const float* __restrict__ Wk,
                          const float* __restrict__ Wv)
{
    const int h = blockIdx.x, mat = blockIdx.y;
    const float* W = ((mat == 0) ? Wq : (mat == 1) ? Wk : Wv) + (size_t)h * DD * DH;
    float* Out = g_Wt + ((size_t)h * 192 + mat * 64) * DD;
    for (int i = threadIdx.x; i < DH * DD; i += blockDim.x) {
        int e = i / DD, d = i % DD;
        Out[i] = tf32r(W[(size_t)d * DH + e]);
    }
}
__global__ void prep_wo(const float* __restrict__ Wo)
{
    const int n = blockIdx.x;
    for (int k = threadIdx.x; k < DD; k += blockDim.x)
        g_Wot[(size_t)n * DD + k] = tf32r(Wo[(size_t)k * DD + n]);
}

// =========================================================================
// GEMM mainloop: C[128 x 192] = A[128 x 768] * Bt[192 x 768]^T
// 256 threads = 8 warps (2m x 4n); warp tile 64 x 48 (4 mt x 6 nt).
// cp.async double-buffered K-chunks of 32. A, Bt pre-rounded tf32.
// SMEM: As[2][128*36] + Bs[2][192*36] = 92160 B.
// =========================================================================
#define GEMM_SMEM (2*128*36*4 + 2*192*36*4)

__device__ __forceinline__ void gemm_issue(const float* __restrict__ A,
                                           const float* __restrict__ Bt,
                                           int c, uint32_t As_u, uint32_t Bs_u,
                                           int tid)
{
    const int buf = c & 1;
    const uint32_t Ad = As_u + buf * (128 * 36 * 4);
    const uint32_t Bd = Bs_u + buf * (192 * 36 * 4);
    const float* Ap = A + c * 32;
    const float* Bp = Bt + c * 32;
    #pragma unroll
    for (int i = 0; i < 4; i++) {
        int fid = tid + i * 256, r = fid >> 3, u = fid & 7;
        cpa16(Ad + (r * 36 + u * 4) * 4, Ap + (size_t)r * DD + u * 4);
    }
    #pragma unroll
    for (int i = 0; i < 6; i++) {
        int fid = tid + i * 256, r = fid >> 3, u = fid & 7;
        cpa16(Bd + (r * 36 + u * 4) * 4, Bp + (size_t)r * DD + u * 4);
    }
    CP_COMMIT();
}

__device__ __forceinline__ void gemm_main(const float* __restrict__ A,
                                          const float* __restrict__ Bt,
                                          float acc[4][6][4], char* smbase)
{
    const int tid = threadIdx.x;
    const int w = tid >> 5, lane = tid & 31;
    const int g = lane >> 2, t = lane & 3;
    const int wm = (w >> 2) * 64, wn = (w & 3) * 48;
    float* As = (float*)smbase;
    float* Bs = As + 2 * 128 * 36;
    const uint32_t As_u = smem_u32(As), Bs_u = smem_u32(Bs);

    #pragma unroll
    for (int mt = 0; mt < 4; mt++)
        #pragma unroll
        for (int nt = 0; nt < 6; nt++)
            #pragma unroll
            for (int i = 0; i < 4; i++) acc[mt][nt][i] = 0.f;

    gemm_issue(A, Bt, 0, As_u, Bs_u, tid);
    for (int c = 0; c < 24; c++) {
        if (c < 23) { gemm_issue(A, Bt, c + 1, As_u, Bs_u, tid); CP_WAIT1(); }
        else CP_WAIT0();
        __syncthreads();
        const float* Ab = As + (c & 1) * 128 * 36;
        const float* Bb = Bs + (c & 1) * 192 * 36;
        #pragma unroll
        for (int ks = 0; ks < 4; ks++) {
            uint32_t af[4][4], bf[6][2];
            #pragma unroll
            for (int mt = 0; mt < 4; mt++) {
                const float* Ar = Ab + (wm + mt * 16 + g) * 36 + ks * 8 + t;
                af[mt][0] = f2u(Ar[0]);
                af[mt][1] = f2u(Ar[8 * 36]);
                af[mt][2] = f2u(Ar[4]);
                af[mt][3] = f2u(Ar[8 * 36 + 4]);
            }
            #pragma unroll
            for (int nt = 0; nt < 6; nt++) {
                const float* Br = Bb + (wn + nt * 8 + g) * 36 + ks * 8 + t;
                bf[nt][0] = f2u(Br[0]);
                bf[nt][1] = f2u(Br[4]);
            }
            #pragma unroll
            for (int mt = 0; mt < 4; mt++)
                #pragma unroll
                for (int nt = 0; nt < 6; nt++)
                    mma_tf32(acc[mt][nt], af[mt], bf[nt]);
        }
        __syncthreads();
    }
}

// ============================ QKV projection ===============================
// grid (8, 12, 16): 128 seq rows x 192 cols (Q|K|V).
__global__ __launch_bounds__(256) void qkv_tc(
    const float* __restrict__ bq, const float* __restrict__ bk,
    const float* __restrict__ bv)
{
    extern __shared__ char smQ[];
    const int m_tile = blockIdx.x, h = blockIdx.y, b = blockIdx.z;
    const int row0 = m_tile * 128;
    const int tid = threadIdx.x;
    const int w = tid >> 5, lane = tid & 31;
    const int g = lane >> 2, t = lane & 3;
    const int wm = (w >> 2) * 64, wn = (w & 3) * 48;

    float acc[4][6][4];
    gemm_main(g_Xr + ((size_t)b * SS + row0) * DD,
              g_Wt + (size_t)h * 192 * DD, acc, smQ);

    #pragma unroll
    for (int nt = 0; nt < 6; nt++) {
        const int eg = wn + nt * 8;
        const int mat = eg >> 6;
        const int e = (eg & 63) + 2 * t;
        const float* bp = (mat == 0) ? bq : (mat == 1) ? bk : bv;
        const float b0 = bp[h * DH + e], b1 = bp[h * DH + e + 1];
        float* Ob = ((mat == 0) ? g_Q : (mat == 1) ? g_K : g_V)
                  + (((size_t)b * HH + h) * SS + row0) * DH;
        #pragma unroll
        for (int mt = 0; mt < 4; mt++) {
            int r = wm + mt * 16 + g;
            *(float2*)&Ob[(size_t)r * DH + e] =
                make_float2(tf32r(acc[mt][nt][0] + b0), tf32r(acc[mt][nt][1] + b1));
            *(float2*)&Ob[(size_t)(r + 8) * DH + e] =
                make_float2(tf32r(acc[mt][nt][2] + b0), tf32r(acc[mt][nt][3] + b1));
        }
    }
}

// ============================ output projection ============================
// grid (128, 4): 128 rows x 192 cols of out = Ctx @ Wo + bo  (fp32, no round)
__global__ __launch_bounds__(256) void proj_tc(
    const float* __restrict__ bo, float* __restrict__ out)
{
    extern __shared__ char smP[];
    const int row0 = blockIdx.x * 128, col0 = blockIdx.y * 192;
    const int tid = threadIdx.x;
    const int w = tid >> 5, lane = tid & 31;
    const int g = lane >> 2, t = lane & 3;
    const int wm = (w >> 2) * 64, wn = (w & 3) * 48;

    float acc[4][6][4];
    gemm_main(g_Ctx + (size_t)row0 * DD, g_Wot + (size_t)col0 * DD, acc, smP);

    #pragma unroll
    for (int nt = 0; nt < 6; nt++) {
        const int e = col0 + wn + nt * 8 + 2 * t;
        const float b0 = bo[e], b1 = bo[e + 1];
        #pragma unroll
        for (int mt = 0; mt < 4; mt++) {
            int r = row0 + wm + mt * 16 + g;
            *(float2*)&out[(size_t)r * DD + e] =
                make_float2(acc[mt][nt][0] + b0, acc[mt][nt][1] + b1);
            *(float2*)&out[(size_t)(r + 8) * DD + e] =
                make_float2(acc[mt][nt][2] + b0, acc[mt][nt][3] + b1);
        }
    }
}

// =========================================================================
// Flash attention, tf32 mma, in-register P redistribution (no P SMEM).
// grid (8, 12, 16), 256 threads, warp = 16 query rows. 16 key tiles of 64.
// Q/K/V pre-rounded tf32 by qkv_tc; scale 1/8 folded into exp.
// SMEM: Qs[128][68] | Ks[64][68] | Vs[64][72]  = 70656 B
// =========================================================================
#define AQ 68
#define AK 68
#define AV 72
#define ATTN_SMEM ((128*AQ + 64*AK + 64*AV) * 4)

__global__ __launch_bounds__(256) void attn_tc()
{
    extern __shared__ float smA[];
    float* Qs = smA;
    float* Ks = Qs + 128 * AQ;
    float* Vs = Ks + 64 * AK;
    const uint32_t Qu = smem_u32(Qs), Ku = smem_u32(Ks), Vu = smem_u32(Vs);

    const int tid = threadIdx.x;
    const int w = tid >> 5, lane = tid & 31;
    const int g = lane >> 2, t = lane & 3;
    const int q0 = blockIdx.x * 128;
    const int h = blockIdx.y, b = blockIdx.z;

    const float* Qg = g_Q + (((size_t)b * HH + h) * SS + q0) * DH;
    const float* Kg = g_K + (((size_t)b * HH + h) * SS) * DH;
    const float* Vg = g_V + (((size_t)b * HH + h) * SS) * DH;

    #pragma unroll
    for (int i = 0; i < 8; i++) {
        int fid = tid + i * 256, r = fid >> 4, u = fid & 15;
        cpa16(Qu + (r * AQ + u * 4) * 4, Qg + (size_t)r * DH + u * 4);
    }
    CP_COMMIT();

    float m0 = -1e30f, m1 = -1e30f, l0 = 0.f, l1 = 0.f;
    float o[8][4];
    #pragma unroll
    for (int i = 0; i < 8; i++)
        #pragma unroll
        for (int j = 0; j < 4; j++) o[i][j] = 0.f;

    const unsigned F = 0xffffffffu;
    const int sA = (lane & ~3) + (t >> 1);
    const int sB = sA + 2;
    const bool odd = t & 1;

    for (int kt = 0; kt < SS; kt += 64) {
        __syncthreads();                      // prev PV done reading Vs
        #pragma unroll
        for (int i = 0; i < 4; i++) {
            int fid = tid + i * 256, r = fid >> 4, u = fid & 15;
            cpa16(Ku + (r * AK + u * 4) * 4, Kg + (size_t)(kt + r) * DH + u * 4);
        }
        #pragma unroll
        for (int i = 0; i < 4; i++) {
            int fid = tid + i * 256, r = fid >> 4, u = fid & 15;
            cpa16(Vu + (r * AV + u * 4) * 4, Vg + (size_t)(kt + r) * DH + u * 4);
        }
        CP_COMMIT(); CP_WAIT0();
        __syncthreads();

        // S = Q @ K^T (unscaled)
        float s[8][4];
        #pragma unroll
        for (int nt = 0; nt < 8; nt++)
            #pragma unroll
            for (int j = 0; j < 4; j++) s[nt][j] = 0.f;
        #pragma unroll
        for (int ks = 0; ks < 8; ks++) {
            uint32_t af[4];
            const float* Ar = Qs + (w * 16 + g) * AQ + ks * 8 + t;
            af[0] = f2u(Ar[0]); af[1] = f2u(Ar[8 * AQ]);
            af[2] = f2u(Ar[4]); af[3] = f2u(Ar[8 * AQ + 4]);
            #pragma unroll
            for (int nt = 0; nt < 8; nt++) {
                uint32_t bf[2];
                const float* Br = Ks + (nt * 8 + g) * AK + ks * 8 + t;
                bf[0] = f2u(Br[0]); bf[1] = f2u(Br[4]);
                mma_tf32(s[nt], af, bf);
            }
        }

        // online softmax (scale folded into exp)
        float mx0 = -1e30f, mx1 = -1e30f;
        #pragma unroll
        for (int nt = 0; nt < 8; nt++) {
            mx0 = fmaxf(mx0, fmaxf(s[nt][0], s[nt][1]));
            mx1 = fmaxf(mx1, fmaxf(s[nt][2], s[nt][3]));
        }
        #pragma unroll
        for (int msk = 1; msk <= 2; msk <<= 1) {
            mx0 = fmaxf(mx0, __shfl_xor_sync(F, mx0, msk));
            mx1 = fmaxf(mx1, __shfl_xor_sync(F, mx1, msk));
        }
        const float mn0 = fmaxf(m0, mx0), mn1 = fmaxf(m1, mx1);
        const float a0 = __expf(0.125f * (m0 - mn0));
        const float a1 = __expf(0.125f * (m1 - mn1));
        float rs0 = 0.f, rs1 = 0.f;
        #pragma unroll
        for (int nt = 0; nt < 8; nt++) {
            float p0 = tf32r(__expf(0.125f * (s[nt][0] - mn0)));
            float p1 = tf32r(__expf(0.125f * (s[nt][1] - mn0)));
            float p2 = tf32r(__expf(0.125f * (s[nt][2] - mn1)));
            float p3 = tf32r(__expf(0.125f * (s[nt][3] - mn1)));
            rs0 += p0 + p1; rs1 += p2 + p3;
            s[nt][0] = p0; s[nt][1] = p1; s[nt][2] = p2; s[nt][3] = p3;
        }
        #pragma unroll
        for (int msk = 1; msk <= 2; msk <<= 1) {
            rs0 += __shfl_xor_sync(F, rs0, msk);
            rs1 += __shfl_xor_sync(F, rs1, msk);
        }
        l0 = l0 * a0 + rs0; l1 = l1 * a1 + rs1;
        m0 = mn0; m1 = mn1;
        #pragma unroll
        for (int nt = 0; nt < 8; nt++) {
            o[nt][0] *= a0; o[nt][1] *= a0;
            o[nt][2] *= a1; o[nt][3] *= a1;
        }

        // O += P @ V — P redistributed C-frag -> A-frag via quad shfl
        #pragma unroll
        for (int ks = 0; ks < 8; ks++) {
            uint32_t af[4];
            {
                float x0 = __shfl_sync(F, s[ks][0], sA);
                float x1 = __shfl_sync(F, s[ks][1], sA);
                af[0] = f2u(odd ? x1 : x0);
                float y0 = __shfl_sync(F, s[ks][2], sA);
                float y1 = __shfl_sync(F, s[ks][3], sA);
                af[1] = f2u(odd ? y1 : y0);
                float z0 = __shfl_sync(F, s[ks][0], sB);
                float z1 = __shfl_sync(F, s[ks][1], sB);
                af[2] = f2u(odd ? z1 : z0);
                float u0 = __shfl_sync(F, s[ks][2], sB);
                float u1 = __shfl_sync(F, s[ks][3], sB);
                af[3] = f2u(odd ? u1 : u0);
            }
            #pragma unroll
            for (int nt = 0; nt < 8; nt++) {
                uint32_t bf[2];
                const float* Br = Vs + (ks * 8 + t) * AV + nt * 8 + g;
                bf[0] = f2u(Br[0]); bf[1] = f2u(Br[4 * AV]);
                mma_tf32(o[nt], af, bf);
            }
        }
    }

    // normalize + write tf32-rounded context [B,S,D] head-concat
    const float inv0 = 1.0f / l0, inv1 = 1.0f / l1;
    float* Cg = g_Ctx + ((size_t)b * SS + q0) * DD + h * DH;
    #pragma unroll
    for (int nt = 0; nt < 8; nt++) {
        int r = w * 16 + g, e = nt * 8 + 2 * t;
        *(float2*)&Cg[(size_t)r * DD + e] =
            make_float2(tf32r(o[nt][0] * inv0), tf32r(o[nt][1] * inv0));
        *(float2*)&Cg[(size_t)(r + 8) * DD + e] =
            make_float2(tf32r(o[nt][2] * inv1), tf32r(o[nt][3] * inv1));
    }
}

// ---------------------------------------------------------------------------
extern "C" void kernel_launch(void* const* d_in, const int* in_sizes, int n_in,
                              void* d_out, int out_size)
{
    const float* X  = (const float*)d_in[0];
    const float* Wq = (const float*)d_in[1];
    const float* bq = (const float*)d_in[2];
    const float* Wk = (const float*)d_in[3];
    const float* bk = (const float*)d_in[4];
    const float* Wv = (const float*)d_in[5];
    const float* bv = (const float*)d_in[6];
    const float* Wo = (const float*)d_in[7];
    const float* bo = (const float*)d_in[8];
    float* out = (float*)d_out;

    cudaFuncSetAttribute(qkv_tc,
                         cudaFuncAttributeMaxDynamicSharedMemorySize, GEMM_SMEM);
    cudaFuncSetAttribute(proj_tc,
                         cudaFuncAttributeMaxDynamicSharedMemorySize, GEMM_SMEM);
    cudaFuncSetAttribute(attn_tc,
                         cudaFuncAttributeMaxDynamicSharedMemorySize, ATTN_SMEM);

    prep_x<<<(BB * SS * DD) / (256 * 4), 256>>>(X);
    prep_wqkv<<<dim3(HH, 3), 256>>>(Wq, Wk, Wv);
    prep_wo<<<DD, 256>>>(Wo);
    qkv_tc<<<dim3(SS / 128, HH, BB), 256, GEMM_SMEM>>>(bq, bk, bv);
    attn_tc<<<dim3(SS / 128, HH, BB), 256, ATTN_SMEM>>>();
    proj_tc<<<dim3(SS * BB / 128, DD / 192), 256, GEMM_SMEM>>>(bo, out);
}